// round 8
// baseline (speedup 1.0000x reference)
#include <cuda_runtime.h>
#include <cstdint>

#define NLVL 16
#define TSZ (1 << 19)
#define TMASK ((1u << 19) - 1u)
#define PRIME_Y 2654435761u
#define PRIME_Z 805459861u

#define BMAX (1 << 20)          // BSZ = 1048576
#define NBINS (1 << 18)         // 64^3 morton bins
#define NCHUNK (NBINS / 1024)   // 256

#define N_COARSE 10             // levels 0..9 (R=16..128): benefit from sort
// levels 10..15 (R=161..512): no corner sharing -> natural order, overlapped

// ---- scratch (device globals; no allocation allowed) ----
__device__ uint32_t g_hist[NBINS];   // histogram -> scanned offsets -> cursors
__device__ uint32_t g_chunk[NCHUNK]; // chunk totals -> exclusive scanned
__device__ float4   g_pts[BMAX];     // sorted (p0,p1,p2, bitcast(orig idx))

// floor(16 * 2^(i/3)); ambiguous i=3,6,9,12,15 -> power-of-two branch
// (validated rel_err 3.9e-8).
__constant__ int c_res[NLVL] = {16, 20, 25, 32, 40, 50, 64, 80,
                                101, 128, 161, 203, 256, 322, 406, 512};

__device__ __forceinline__ uint32_t spread3(uint32_t v) {
    v &= 0x3FFu;
    v = (v | (v << 16)) & 0x030000FFu;
    v = (v | (v << 8))  & 0x0300F00Fu;
    v = (v | (v << 4))  & 0x030C30C3u;
    v = (v | (v << 2))  & 0x09249249u;
    return v;
}

__device__ __forceinline__ uint32_t morton64(float p0, float p1, float p2) {
    uint32_t c0 = (uint32_t)fminf(fmaxf(floorf((p0 + 1.0f) * 32.0f), 0.0f), 63.0f);
    uint32_t c1 = (uint32_t)fminf(fmaxf(floorf((p1 + 1.0f) * 32.0f), 0.0f), 63.0f);
    uint32_t c2 = (uint32_t)fminf(fmaxf(floorf((p2 + 1.0f) * 32.0f), 0.0f), 63.0f);
    return spread3(c0) | (spread3(c1) << 1) | (spread3(c2) << 2);
}

// ---- K1: histogram ----
__global__ void k_hist(const float* __restrict__ x, int B) {
    int b = blockIdx.x * blockDim.x + threadIdx.x;
    if (b >= B) return;
    atomicAdd(&g_hist[morton64(x[3 * b], x[3 * b + 1], x[3 * b + 2])], 1u);
}

// ---- K2: per-1024-bin chunk exclusive scan (in place) + chunk totals ----
__global__ void k_scan_chunks() {
    __shared__ uint32_t s[1024];
    const int t = threadIdx.x;
    const int base = blockIdx.x * 1024;
    const uint32_t v = g_hist[base + t];
    s[t] = v;
    __syncthreads();
    #pragma unroll
    for (int o = 1; o < 1024; o <<= 1) {
        uint32_t u = (t >= o) ? s[t - o] : 0u;
        __syncthreads();
        s[t] += u;
        __syncthreads();
    }
    g_hist[base + t] = s[t] - v;                 // exclusive within chunk
    if (t == 1023) g_chunk[blockIdx.x] = s[1023];
}

// ---- K3: exclusive scan of the 256 chunk totals ----
__global__ void k_scan_top() {
    __shared__ uint32_t s[NCHUNK];
    const int t = threadIdx.x;
    const uint32_t v = g_chunk[t];
    s[t] = v;
    __syncthreads();
    #pragma unroll
    for (int o = 1; o < NCHUNK; o <<= 1) {
        uint32_t u = (t >= o) ? s[t - o] : 0u;
        __syncthreads();
        s[t] += u;
        __syncthreads();
    }
    g_chunk[t] = s[t] - v;
}

// ---- K4: scatter sorted point records (coords + original idx) ----
__global__ void k_scatter(const float* __restrict__ x, int B) {
    int b = blockIdx.x * blockDim.x + threadIdx.x;
    if (b >= B) return;
    const float p0 = x[3 * b + 0];
    const float p1 = x[3 * b + 1];
    const float p2 = x[3 * b + 2];
    const uint32_t m = morton64(p0, p1, p2);
    const uint32_t pos = g_chunk[m >> 10] + atomicAdd(&g_hist[m], 1u);
    g_pts[pos] = make_float4(p0, p1, p2, __uint_as_float((uint32_t)b));
}

// ---- gather: one level, plain 8x LDG.64 (round-4 pair-merge regressed) ----
__device__ __forceinline__ void level_gather(
    float p0, float p1, float p2, int R, const float2* __restrict__ tab,
    float& a0, float& a1)
{
    const float scale = 0.5f * (float)R;
    const float r0 = (p0 + 1.0f) * scale;
    const float r1 = (p1 + 1.0f) * scale;
    const float r2 = (p2 + 1.0f) * scale;

    float f0 = floorf(r0);
    float f1 = floorf(r1);
    float f2 = floorf(r2);
    const float rmax = (float)(R - 1);
    f0 = fminf(fmaxf(f0, 0.0f), rmax);
    f1 = fminf(fmaxf(f1, 0.0f), rmax);
    f2 = fminf(fmaxf(f2, 0.0f), rmax);

    const float w0 = r0 - f0, w1 = r1 - f1, w2 = r2 - f2;
    const float u0 = 1.0f - w0, u1 = 1.0f - w1, u2 = 1.0f - w2;

    const uint32_t i0 = (uint32_t)f0;
    const uint32_t i1 = (uint32_t)f1;
    const uint32_t i2 = (uint32_t)f2;

    const uint32_t xa = i0;
    const uint32_t xb = i0 + 1u;
    const uint32_t ya = i1 * PRIME_Y;
    const uint32_t yb = ya + PRIME_Y;
    const uint32_t za = i2 * PRIME_Z;
    const uint32_t zb = za + PRIME_Z;

    const float2 v000 = __ldg(&tab[(xa ^ ya ^ za) & TMASK]);
    const float2 v100 = __ldg(&tab[(xb ^ ya ^ za) & TMASK]);
    const float2 v010 = __ldg(&tab[(xa ^ yb ^ za) & TMASK]);
    const float2 v110 = __ldg(&tab[(xb ^ yb ^ za) & TMASK]);
    const float2 v001 = __ldg(&tab[(xa ^ ya ^ zb) & TMASK]);
    const float2 v101 = __ldg(&tab[(xb ^ ya ^ zb) & TMASK]);
    const float2 v011 = __ldg(&tab[(xa ^ yb ^ zb) & TMASK]);
    const float2 v111 = __ldg(&tab[(xb ^ yb ^ zb) & TMASK]);

    const float w000 = u0 * u1 * u2;
    const float w100 = w0 * u1 * u2;
    const float w010 = u0 * w1 * u2;
    const float w110 = w0 * w1 * u2;
    const float w001 = u0 * u1 * w2;
    const float w101 = w0 * u1 * w2;
    const float w011 = u0 * w1 * w2;
    const float w111 = w0 * w1 * w2;

    a0 = w000 * v000.x;
    a1 = w000 * v000.y;
    a0 = fmaf(w100, v100.x, a0);  a1 = fmaf(w100, v100.y, a1);
    a0 = fmaf(w010, v010.x, a0);  a1 = fmaf(w010, v010.y, a1);
    a0 = fmaf(w110, v110.x, a0);  a1 = fmaf(w110, v110.y, a1);
    a0 = fmaf(w001, v001.x, a0);  a1 = fmaf(w001, v001.y, a1);
    a0 = fmaf(w101, v101.x, a0);  a1 = fmaf(w101, v101.y, a1);
    a0 = fmaf(w011, v011.x, a0);  a1 = fmaf(w011, v011.y, a1);
    a0 = fmaf(w111, v111.x, a0);  a1 = fmaf(w111, v111.y, a1);
}

// ---- K5a: coarse levels (0..9) over morton-sorted point records ----
__global__ __launch_bounds__(256, 3) void k_coarse(
    const float* __restrict__ emb,
    float* __restrict__ out,
    int B)
{
    int b = blockIdx.x * blockDim.x + threadIdx.x;
    if (b >= B) return;

    const float4 pt = __ldg(&g_pts[b]);
    const float p0 = pt.x, p1 = pt.y, p2 = pt.z;
    const uint32_t idx = __float_as_uint(pt.w);

    float4* __restrict__ o = reinterpret_cast<float4*>(out) + (size_t)idx * 8;

    #pragma unroll 1
    for (int g = 0; g < N_COARSE / 2; ++g) {
        const int l0 = 2 * g;
        const int R0 = c_res[l0];
        const int R1 = c_res[l0 + 1];
        const float2* __restrict__ tab0 =
            reinterpret_cast<const float2*>(emb) + (size_t)l0 * TSZ;
        const float2* __restrict__ tab1 = tab0 + TSZ;

        float a0, a1, a2, a3;
        level_gather(p0, p1, p2, R0, tab0, a0, a1);
        level_gather(p0, p1, p2, R1, tab1, a2, a3);
        __stcs(&o[g], make_float4(a0, a1, a2, a3));
    }
}

// ---- K5b: fine levels (10..15), natural order, no sort dependency ----
__global__ __launch_bounds__(256, 3) void k_fine(
    const float* __restrict__ x,
    const float* __restrict__ emb,
    float* __restrict__ out,
    int B)
{
    int b = blockIdx.x * blockDim.x + threadIdx.x;
    if (b >= B) return;

    const float p0 = x[3 * b + 0];   // coalesced
    const float p1 = x[3 * b + 1];
    const float p2 = x[3 * b + 2];

    float4* __restrict__ o = reinterpret_cast<float4*>(out) + (size_t)b * 8;

    #pragma unroll 1
    for (int g = N_COARSE / 2; g < NLVL / 2; ++g) {
        const int l0 = 2 * g;
        const int R0 = c_res[l0];
        const int R1 = c_res[l0 + 1];
        const float2* __restrict__ tab0 =
            reinterpret_cast<const float2*>(emb) + (size_t)l0 * TSZ;
        const float2* __restrict__ tab1 = tab0 + TSZ;

        float a0, a1, a2, a3;
        level_gather(p0, p1, p2, R0, tab0, a0, a1);
        level_gather(p0, p1, p2, R1, tab1, a2, a3);
        __stcs(&o[g], make_float4(a0, a1, a2, a3));
    }
}

extern "C" void kernel_launch(void* const* d_in, const int* in_sizes, int n_in,
                              void* d_out, int out_size)
{
    const float* x   = (const float*)d_in[0];   // (B, 3) f32
    const float* emb = (const float*)d_in[1];   // (16, 2^19, 2) f32
    float* out = (float*)d_out;                 // (B, 32) f32

    const int B = in_sizes[0] / 3;
    const int threads = 256;
    const int blocks = (B + threads - 1) / threads;

    // second stream + fork/join events (created once; host-side objects only,
    // no device memory)
    static cudaStream_t s2 = nullptr;
    static cudaEvent_t ev_fork = nullptr, ev_join = nullptr;
    if (s2 == nullptr) {
        cudaStreamCreateWithFlags(&s2, cudaStreamNonBlocking);
        cudaEventCreateWithFlags(&ev_fork, cudaEventDisableTiming);
        cudaEventCreateWithFlags(&ev_join, cudaEventDisableTiming);
    }

    // Fork: fine-level gather has NO dependency on the sort -> run it
    // concurrently on s2 while the sort pipeline + coarse gather run on the
    // main stream. Join before returning.
    cudaEventRecord(ev_fork, 0);
    cudaStreamWaitEvent(s2, ev_fork, 0);
    k_fine<<<blocks, threads, 0, s2>>>(x, emb, out, B);
    cudaEventRecord(ev_join, s2);

    // main stream: sort pipeline + coarse gather
    void* hist_ptr = nullptr;
    cudaGetSymbolAddress(&hist_ptr, g_hist);
    cudaMemsetAsync(hist_ptr, 0, NBINS * sizeof(uint32_t));

    k_hist<<<blocks, threads>>>(x, B);
    k_scan_chunks<<<NCHUNK, 1024>>>();
    k_scan_top<<<1, NCHUNK>>>();
    k_scatter<<<blocks, threads>>>(x, B);
    k_coarse<<<blocks, threads>>>(emb, out, B);

    cudaStreamWaitEvent(0, ev_join, 0);
}

// round 11
// speedup vs baseline: 1.1870x; 1.1870x over previous
#include <cuda_runtime.h>
#include <cstdint>

#define NLVL 16
#define TSZ (1 << 19)
#define TMASK ((1u << 19) - 1u)
#define PRIME_Y 2654435761u
#define PRIME_Z 805459861u

#define BMAX (1 << 20)          // BSZ = 1048576
#define NBINS (1 << 15)         // 32^3 morton bins (warp extent unchanged vs 64^3)
#define NCHUNK (NBINS / 1024)   // 32

// ---- scratch (device globals; no allocation allowed) ----
__device__ uint32_t g_hist[NBINS];   // histogram -> scanned offsets -> cursors
__device__ uint32_t g_chunk[NCHUNK]; // chunk totals -> exclusive scanned
__device__ float4   g_pts[BMAX];     // sorted (p0,p1,p2, bitcast(orig idx))

// floor(16 * 2^(i/3)); ambiguous i=3,6,9,12,15 -> power-of-two branch
// (validated rel_err 3.9e-8).
__constant__ int c_res[NLVL] = {16, 20, 25, 32, 40, 50, 64, 80,
                                101, 128, 161, 203, 256, 322, 406, 512};

__device__ __forceinline__ uint32_t spread3(uint32_t v) {
    v &= 0x3FFu;
    v = (v | (v << 16)) & 0x030000FFu;
    v = (v | (v << 8))  & 0x0300F00Fu;
    v = (v | (v << 4))  & 0x030C30C3u;
    v = (v | (v << 2))  & 0x09249249u;
    return v;
}

__device__ __forceinline__ uint32_t morton32(float p0, float p1, float p2) {
    uint32_t c0 = (uint32_t)fminf(fmaxf(floorf((p0 + 1.0f) * 16.0f), 0.0f), 31.0f);
    uint32_t c1 = (uint32_t)fminf(fmaxf(floorf((p1 + 1.0f) * 16.0f), 0.0f), 31.0f);
    uint32_t c2 = (uint32_t)fminf(fmaxf(floorf((p2 + 1.0f) * 16.0f), 0.0f), 31.0f);
    return spread3(c0) | (spread3(c1) << 1) | (spread3(c2) << 2);   // 15-bit key
}

// ---- K1: histogram ----
__global__ void k_hist(const float* __restrict__ x, int B) {
    int b = blockIdx.x * blockDim.x + threadIdx.x;
    if (b >= B) return;
    atomicAdd(&g_hist[morton32(__ldg(&x[3 * b]), __ldg(&x[3 * b + 1]),
                               __ldg(&x[3 * b + 2]))], 1u);
}

// ---- K2: per-1024-bin chunk exclusive scan (in place) + chunk totals ----
__global__ void k_scan_chunks() {
    __shared__ uint32_t s[1024];
    const int t = threadIdx.x;
    const int base = blockIdx.x * 1024;
    const uint32_t v = g_hist[base + t];
    s[t] = v;
    __syncthreads();
    #pragma unroll
    for (int o = 1; o < 1024; o <<= 1) {
        uint32_t u = (t >= o) ? s[t - o] : 0u;
        __syncthreads();
        s[t] += u;
        __syncthreads();
    }
    g_hist[base + t] = s[t] - v;                 // exclusive within chunk
    if (t == 1023) g_chunk[blockIdx.x] = s[1023];
}

// ---- K3: exclusive warp-scan of the 32 chunk totals ----
__global__ void k_scan_top() {
    const int t = threadIdx.x;                   // 32 threads
    const uint32_t v = g_chunk[t];
    uint32_t s = v;
    #pragma unroll
    for (int o = 1; o < 32; o <<= 1) {
        uint32_t u = __shfl_up_sync(0xFFFFFFFFu, s, o);
        if (t >= o) s += u;
    }
    g_chunk[t] = s - v;
}

// ---- K4: scatter sorted point records (coords + original idx) ----
__global__ void k_scatter(const float* __restrict__ x, int B) {
    int b = blockIdx.x * blockDim.x + threadIdx.x;
    if (b >= B) return;
    const float p0 = x[3 * b + 0];
    const float p1 = x[3 * b + 1];
    const float p2 = x[3 * b + 2];
    const uint32_t m = morton32(p0, p1, p2);
    const uint32_t pos = g_chunk[m >> 10] + atomicAdd(&g_hist[m], 1u);
    __stcs(&g_pts[pos], make_float4(p0, p1, p2, __uint_as_float((uint32_t)b)));
}

// ---- level helpers ----
// Computes 8 corner hashes + 8 trilerp weights; returns packed cell key.
__device__ __forceinline__ uint32_t level_prep(
    float p0, float p1, float p2, int R,
    uint32_t* __restrict__ h, float* __restrict__ w)
{
    const float scale = 0.5f * (float)R;
    const float r0 = (p0 + 1.0f) * scale;
    const float r1 = (p1 + 1.0f) * scale;
    const float r2 = (p2 + 1.0f) * scale;

    float f0 = floorf(r0);
    float f1 = floorf(r1);
    float f2 = floorf(r2);
    const float rmax = (float)(R - 1);
    f0 = fminf(fmaxf(f0, 0.0f), rmax);
    f1 = fminf(fmaxf(f1, 0.0f), rmax);
    f2 = fminf(fmaxf(f2, 0.0f), rmax);

    const float w0 = r0 - f0, w1 = r1 - f1, w2 = r2 - f2;
    const float u0 = 1.0f - w0, u1 = 1.0f - w1, u2 = 1.0f - w2;

    const uint32_t i0 = (uint32_t)f0;
    const uint32_t i1 = (uint32_t)f1;
    const uint32_t i2 = (uint32_t)f2;

    const uint32_t xa = i0;
    const uint32_t xb = i0 + 1u;
    const uint32_t ya = i1 * PRIME_Y;
    const uint32_t yb = ya + PRIME_Y;
    const uint32_t za = i2 * PRIME_Z;
    const uint32_t zb = za + PRIME_Z;

    h[0] = (xa ^ ya ^ za) & TMASK;
    h[1] = (xb ^ ya ^ za) & TMASK;
    h[2] = (xa ^ yb ^ za) & TMASK;
    h[3] = (xb ^ yb ^ za) & TMASK;
    h[4] = (xa ^ ya ^ zb) & TMASK;
    h[5] = (xb ^ ya ^ zb) & TMASK;
    h[6] = (xa ^ yb ^ zb) & TMASK;
    h[7] = (xb ^ yb ^ zb) & TMASK;

    w[0] = u0 * u1 * u2;
    w[1] = w0 * u1 * u2;
    w[2] = u0 * w1 * u2;
    w[3] = w0 * w1 * u2;
    w[4] = u0 * u1 * w2;
    w[5] = w0 * u1 * w2;
    w[6] = u0 * w1 * w2;
    w[7] = w0 * w1 * w2;

    return i0 | (i1 << 10) | (i2 << 20);
}

__device__ __forceinline__ void load8(
    const float2* __restrict__ tab, const uint32_t* __restrict__ h,
    float2* __restrict__ v)
{
    #pragma unroll
    for (int k = 0; k < 8; ++k) v[k] = __ldg(&tab[h[k]]);
}

__device__ __forceinline__ void trilerp(
    const float2* __restrict__ v, const float* __restrict__ w,
    float& a0, float& a1)
{
    a0 = w[0] * v[0].x;
    a1 = w[0] * v[0].y;
    #pragma unroll
    for (int k = 1; k < 8; ++k) {
        a0 = fmaf(w[k], v[k].x, a0);
        a1 = fmaf(w[k], v[k].y, a1);
    }
}

// Paired level: point A always loads; point B reuses A's corner VALUES when
// the whole warp agrees both points share the cell (uniform branch -> the
// second 8 loads are skipped entirely, attacking the LDG issue floor).
__device__ __forceinline__ void level_paired(
    const float2* __restrict__ tab, int R,
    float A0, float A1, float A2, float B0, float B1, float B2,
    float& aA0, float& aA1, float& aB0, float& aB1)
{
    uint32_t hA[8], hB[8];
    float wA[8], wB[8];
    const uint32_t kA = level_prep(A0, A1, A2, R, hA, wA);
    const uint32_t kB = level_prep(B0, B1, B2, R, hB, wB);

    float2 vA[8];
    load8(tab, hA, vA);
    trilerp(vA, wA, aA0, aA1);

    if (__all_sync(0xFFFFFFFFu, kA == kB)) {
        trilerp(vA, wB, aB0, aB1);        // same cell -> reuse values
    } else {
        float2 vB[8];
        load8(tab, hB, vB);
        trilerp(vB, wB, aB0, aB1);
    }
}

__device__ __forceinline__ void level_plain(
    const float2* __restrict__ tab, int R,
    float p0, float p1, float p2, float& a0, float& a1)
{
    uint32_t h[8];
    float w[8];
    level_prep(p0, p1, p2, R, h, w);
    float2 v[8];
    load8(tab, h, v);
    trilerp(v, w, a0, a1);
}

// ---- K5: main gather, 2 adjacent sorted points per thread ----
__global__ __launch_bounds__(256, 2) void k_main(
    const float* __restrict__ emb,
    float* __restrict__ out,
    int B)
{
    const int nPairs = (B + 1) >> 1;
    int t = blockIdx.x * blockDim.x + threadIdx.x;
    if (t >= nPairs) t = nPairs - 1;   // clamp: keeps warps full for __all_sync
                                       // (duplicate threads rewrite same rows)

    const int bA = 2 * t;
    const int bB = (2 * t + 1 < B) ? 2 * t + 1 : bA;

    const float4 ptA = __ldg(&g_pts[bA]);
    const float4 ptB = __ldg(&g_pts[bB]);
    const uint32_t idxA = __float_as_uint(ptA.w);
    const uint32_t idxB = __float_as_uint(ptB.w);

    float4* __restrict__ oA = reinterpret_cast<float4*>(out) + (size_t)idxA * 8;
    float4* __restrict__ oB = reinterpret_cast<float4*>(out) + (size_t)idxB * 8;

    #pragma unroll 1
    for (int g = 0; g < NLVL / 2; ++g) {
        const int l0 = 2 * g;
        const int R0 = c_res[l0];
        const int R1 = c_res[l0 + 1];
        const float2* __restrict__ tab0 =
            reinterpret_cast<const float2*>(emb) + (size_t)l0 * TSZ;
        const float2* __restrict__ tab1 = tab0 + TSZ;

        float aA0, aA1, aA2, aA3, aB0, aB1, aB2, aB3;

        if (g < 3) {   // levels 0..5 (R=16..50): corner sharing pays
            level_paired(tab0, R0, ptA.x, ptA.y, ptA.z, ptB.x, ptB.y, ptB.z,
                         aA0, aA1, aB0, aB1);
            level_paired(tab1, R1, ptA.x, ptA.y, ptA.z, ptB.x, ptB.y, ptB.z,
                         aA2, aA3, aB2, aB3);
        } else {       // fine levels: no sharing exists
            level_plain(tab0, R0, ptA.x, ptA.y, ptA.z, aA0, aA1);
            level_plain(tab0, R0, ptB.x, ptB.y, ptB.z, aB0, aB1);
            level_plain(tab1, R1, ptA.x, ptA.y, ptA.z, aA2, aA3);
            level_plain(tab1, R1, ptB.x, ptB.y, ptB.z, aB2, aB3);
        }

        __stcs(&oA[g], make_float4(aA0, aA1, aA2, aA3));
        __stcs(&oB[g], make_float4(aB0, aB1, aB2, aB3));
    }
}

extern "C" void kernel_launch(void* const* d_in, const int* in_sizes, int n_in,
                              void* d_out, int out_size)
{
    const float* x   = (const float*)d_in[0];   // (B, 3) f32
    const float* emb = (const float*)d_in[1];   // (16, 2^19, 2) f32
    float* out = (float*)d_out;                 // (B, 32) f32

    const int B = in_sizes[0] / 3;
    const int threads = 256;
    const int blocks = (B + threads - 1) / threads;
    const int nPairs = (B + 1) >> 1;
    const int blocksP = (nPairs + threads - 1) / threads;

    void* hist_ptr = nullptr;
    cudaGetSymbolAddress(&hist_ptr, g_hist);
    cudaMemsetAsync(hist_ptr, 0, NBINS * sizeof(uint32_t));

    k_hist<<<blocks, threads>>>(x, B);
    k_scan_chunks<<<NCHUNK, 1024>>>();
    k_scan_top<<<1, 32>>>();
    k_scatter<<<blocks, threads>>>(x, B);
    k_main<<<blocksP, threads>>>(emb, out, B);
}

// round 14
// speedup vs baseline: 1.2735x; 1.0729x over previous
#include <cuda_runtime.h>
#include <cstdint>

#define NLVL 16
#define TSZ (1 << 19)
#define TMASK ((1u << 19) - 1u)
#define PRIME_Y 2654435761u
#define PRIME_Z 805459861u

#define BMAX (1 << 20)          // BSZ = 1048576
#define NBINS (1 << 15)         // 32^3 morton bins (same warp spatial extent as 64^3)
#define NCHUNK (NBINS / 1024)   // 32

// ---- scratch (device globals; no allocation allowed) ----
__device__ uint32_t g_hist[NBINS];   // histogram -> scanned offsets -> cursors
__device__ uint32_t g_chunk[NCHUNK]; // chunk totals -> exclusive scanned
__device__ float4   g_pts[BMAX];     // sorted (p0,p1,p2, bitcast(orig idx))

// floor(16 * 2^(i/3)); ambiguous i=3,6,9,12,15 -> power-of-two branch
// (validated rel_err 3.9e-8).
__constant__ int c_res[NLVL] = {16, 20, 25, 32, 40, 50, 64, 80,
                                101, 128, 161, 203, 256, 322, 406, 512};

__device__ __forceinline__ uint32_t spread3(uint32_t v) {
    v &= 0x3FFu;
    v = (v | (v << 16)) & 0x030000FFu;
    v = (v | (v << 8))  & 0x0300F00Fu;
    v = (v | (v << 4))  & 0x030C30C3u;
    v = (v | (v << 2))  & 0x09249249u;
    return v;
}

__device__ __forceinline__ uint32_t morton32(float p0, float p1, float p2) {
    uint32_t c0 = (uint32_t)fminf(fmaxf(floorf((p0 + 1.0f) * 16.0f), 0.0f), 31.0f);
    uint32_t c1 = (uint32_t)fminf(fmaxf(floorf((p1 + 1.0f) * 16.0f), 0.0f), 31.0f);
    uint32_t c2 = (uint32_t)fminf(fmaxf(floorf((p2 + 1.0f) * 16.0f), 0.0f), 31.0f);
    return spread3(c0) | (spread3(c1) << 1) | (spread3(c2) << 2);   // 15-bit key
}

// ---- K1: histogram ----
__global__ void k_hist(const float* __restrict__ x, int B) {
    int b = blockIdx.x * blockDim.x + threadIdx.x;
    if (b >= B) return;
    atomicAdd(&g_hist[morton32(__ldg(&x[3 * b]), __ldg(&x[3 * b + 1]),
                               __ldg(&x[3 * b + 2]))], 1u);
}

// ---- K2: per-1024-bin chunk exclusive scan (in place) + chunk totals ----
__global__ void k_scan_chunks() {
    __shared__ uint32_t s[1024];
    const int t = threadIdx.x;
    const int base = blockIdx.x * 1024;
    const uint32_t v = g_hist[base + t];
    s[t] = v;
    __syncthreads();
    #pragma unroll
    for (int o = 1; o < 1024; o <<= 1) {
        uint32_t u = (t >= o) ? s[t - o] : 0u;
        __syncthreads();
        s[t] += u;
        __syncthreads();
    }
    g_hist[base + t] = s[t] - v;                 // exclusive within chunk
    if (t == 1023) g_chunk[blockIdx.x] = s[1023];
}

// ---- K3: exclusive warp-scan of the 32 chunk totals ----
__global__ void k_scan_top() {
    const int t = threadIdx.x;                   // 32 threads
    const uint32_t v = g_chunk[t];
    uint32_t s = v;
    #pragma unroll
    for (int o = 1; o < 32; o <<= 1) {
        uint32_t u = __shfl_up_sync(0xFFFFFFFFu, s, o);
        if (t >= o) s += u;
    }
    g_chunk[t] = s - v;
}

// ---- K4: scatter sorted point records (coords + original idx) ----
__global__ void k_scatter(const float* __restrict__ x, int B) {
    int b = blockIdx.x * blockDim.x + threadIdx.x;
    if (b >= B) return;
    const float p0 = x[3 * b + 0];
    const float p1 = x[3 * b + 1];
    const float p2 = x[3 * b + 2];
    const uint32_t m = morton32(p0, p1, p2);
    const uint32_t pos = g_chunk[m >> 10] + atomicAdd(&g_hist[m], 1u);
    __stcs(&g_pts[pos], make_float4(p0, p1, p2, __uint_as_float((uint32_t)b)));
}

// ---- gather: one level, plain 8x LDG.64 (round-6 proven form; pair-merge
//      and 2-pt pairing both regressed -> keep it simple, throughput-bound) ----
__device__ __forceinline__ void level_gather(
    float p0, float p1, float p2, int R, const float2* __restrict__ tab,
    float& a0, float& a1)
{
    const float scale = 0.5f * (float)R;
    const float r0 = (p0 + 1.0f) * scale;
    const float r1 = (p1 + 1.0f) * scale;
    const float r2 = (p2 + 1.0f) * scale;

    float f0 = floorf(r0);
    float f1 = floorf(r1);
    float f2 = floorf(r2);
    const float rmax = (float)(R - 1);
    f0 = fminf(fmaxf(f0, 0.0f), rmax);
    f1 = fminf(fmaxf(f1, 0.0f), rmax);
    f2 = fminf(fmaxf(f2, 0.0f), rmax);

    const float w0 = r0 - f0, w1 = r1 - f1, w2 = r2 - f2;
    const float u0 = 1.0f - w0, u1 = 1.0f - w1, u2 = 1.0f - w2;

    const uint32_t i0 = (uint32_t)f0;
    const uint32_t i1 = (uint32_t)f1;
    const uint32_t i2 = (uint32_t)f2;

    const uint32_t xa = i0;
    const uint32_t xb = i0 + 1u;
    const uint32_t ya = i1 * PRIME_Y;
    const uint32_t yb = ya + PRIME_Y;
    const uint32_t za = i2 * PRIME_Z;
    const uint32_t zb = za + PRIME_Z;

    const float2 v000 = __ldg(&tab[(xa ^ ya ^ za) & TMASK]);
    const float2 v100 = __ldg(&tab[(xb ^ ya ^ za) & TMASK]);
    const float2 v010 = __ldg(&tab[(xa ^ yb ^ za) & TMASK]);
    const float2 v110 = __ldg(&tab[(xb ^ yb ^ za) & TMASK]);
    const float2 v001 = __ldg(&tab[(xa ^ ya ^ zb) & TMASK]);
    const float2 v101 = __ldg(&tab[(xb ^ ya ^ zb) & TMASK]);
    const float2 v011 = __ldg(&tab[(xa ^ yb ^ zb) & TMASK]);
    const float2 v111 = __ldg(&tab[(xb ^ yb ^ zb) & TMASK]);

    const float w000 = u0 * u1 * u2;
    const float w100 = w0 * u1 * u2;
    const float w010 = u0 * w1 * u2;
    const float w110 = w0 * w1 * u2;
    const float w001 = u0 * u1 * w2;
    const float w101 = w0 * u1 * w2;
    const float w011 = u0 * w1 * w2;
    const float w111 = w0 * w1 * w2;

    a0 = w000 * v000.x;
    a1 = w000 * v000.y;
    a0 = fmaf(w100, v100.x, a0);  a1 = fmaf(w100, v100.y, a1);
    a0 = fmaf(w010, v010.x, a0);  a1 = fmaf(w010, v010.y, a1);
    a0 = fmaf(w110, v110.x, a0);  a1 = fmaf(w110, v110.y, a1);
    a0 = fmaf(w001, v001.x, a0);  a1 = fmaf(w001, v001.y, a1);
    a0 = fmaf(w101, v101.x, a0);  a1 = fmaf(w101, v101.y, a1);
    a0 = fmaf(w011, v011.x, a0);  a1 = fmaf(w011, v011.y, a1);
    a0 = fmaf(w111, v111.x, a0);  a1 = fmaf(w111, v111.y, a1);
}

// ---- K5: main gather over morton-sorted point records (round-6 form) ----
__global__ __launch_bounds__(256, 3) void hash_embed_kernel(
    const float* __restrict__ emb,
    float* __restrict__ out,
    int B)
{
    int b = blockIdx.x * blockDim.x + threadIdx.x;
    if (b >= B) return;

    const float4 pt = __ldg(&g_pts[b]);          // fully coalesced point read
    const float p0 = pt.x, p1 = pt.y, p2 = pt.z;
    const uint32_t idx = __float_as_uint(pt.w);

    float4* __restrict__ o = reinterpret_cast<float4*>(out) + (size_t)idx * 8;

    #pragma unroll 1
    for (int g = 0; g < NLVL / 2; ++g) {
        const int l0 = 2 * g;
        const int R0 = c_res[l0];
        const int R1 = c_res[l0 + 1];
        const float2* __restrict__ tab0 =
            reinterpret_cast<const float2*>(emb) + (size_t)l0 * TSZ;
        const float2* __restrict__ tab1 = tab0 + TSZ;

        float a0, a1, a2, a3;
        level_gather(p0, p1, p2, R0, tab0, a0, a1);
        level_gather(p0, p1, p2, R1, tab1, a2, a3);

        // streaming store: evict-first, keep tables resident in L2
        __stcs(&o[g], make_float4(a0, a1, a2, a3));
    }
}

extern "C" void kernel_launch(void* const* d_in, const int* in_sizes, int n_in,
                              void* d_out, int out_size)
{
    const float* x   = (const float*)d_in[0];   // (B, 3) f32
    const float* emb = (const float*)d_in[1];   // (16, 2^19, 2) f32
    float* out = (float*)d_out;                 // (B, 32) f32

    const int B = in_sizes[0] / 3;
    const int threads = 256;
    const int blocks = (B + threads - 1) / threads;

    void* hist_ptr = nullptr;
    cudaGetSymbolAddress(&hist_ptr, g_hist);
    cudaMemsetAsync(hist_ptr, 0, NBINS * sizeof(uint32_t));

    k_hist<<<blocks, threads>>>(x, B);
    k_scan_chunks<<<NCHUNK, 1024>>>();
    k_scan_top<<<1, 32>>>();
    k_scatter<<<blocks, threads>>>(x, B);
    hash_embed_kernel<<<blocks, threads>>>(emb, out, B);
}

// round 15
// speedup vs baseline: 1.3377x; 1.0504x over previous
#include <cuda_runtime.h>
#include <cstdint>

#define NLVL 16
#define TSZ (1 << 19)
#define TMASK ((1u << 19) - 1u)
#define PRIME_Y 2654435761u
#define PRIME_Z 805459861u

#define BMAX (1 << 20)          // BSZ = 1048576
#define NBINS (1 << 18)         // 64^3 morton bins (round-6 proven: 4 pts/bin,
                                // no atomic contention; 32^3 regressed scatter)
#define NCHUNK (NBINS / 1024)   // 256

// ---- scratch (device globals; no allocation allowed) ----
__device__ uint32_t g_hist[NBINS];   // histogram -> scanned offsets -> cursors
__device__ uint32_t g_chunk[NCHUNK]; // chunk totals -> exclusive scanned
__device__ float4   g_pts[BMAX];     // sorted (p0,p1,p2, bitcast(orig idx))

// floor(16 * 2^(i/3)); ambiguous i=3,6,9,12,15 -> power-of-two branch
// (validated rel_err 3.9e-8).
__constant__ int c_res[NLVL] = {16, 20, 25, 32, 40, 50, 64, 80,
                                101, 128, 161, 203, 256, 322, 406, 512};

__device__ __forceinline__ uint32_t spread3(uint32_t v) {
    v &= 0x3FFu;
    v = (v | (v << 16)) & 0x030000FFu;
    v = (v | (v << 8))  & 0x0300F00Fu;
    v = (v | (v << 4))  & 0x030C30C3u;
    v = (v | (v << 2))  & 0x09249249u;
    return v;
}

__device__ __forceinline__ uint32_t morton64(float p0, float p1, float p2) {
    uint32_t c0 = (uint32_t)fminf(fmaxf(floorf((p0 + 1.0f) * 32.0f), 0.0f), 63.0f);
    uint32_t c1 = (uint32_t)fminf(fmaxf(floorf((p1 + 1.0f) * 32.0f), 0.0f), 63.0f);
    uint32_t c2 = (uint32_t)fminf(fmaxf(floorf((p2 + 1.0f) * 32.0f), 0.0f), 63.0f);
    return spread3(c0) | (spread3(c1) << 1) | (spread3(c2) << 2);
}

// ---- K1: histogram ----
__global__ void k_hist(const float* __restrict__ x, int B) {
    int b = blockIdx.x * blockDim.x + threadIdx.x;
    if (b >= B) return;
    atomicAdd(&g_hist[morton64(x[3 * b], x[3 * b + 1], x[3 * b + 2])], 1u);
}

// ---- K2: per-1024-bin chunk exclusive scan (in place) + chunk totals ----
__global__ void k_scan_chunks() {
    __shared__ uint32_t s[1024];
    const int t = threadIdx.x;
    const int base = blockIdx.x * 1024;
    const uint32_t v = g_hist[base + t];
    s[t] = v;
    __syncthreads();
    #pragma unroll
    for (int o = 1; o < 1024; o <<= 1) {
        uint32_t u = (t >= o) ? s[t - o] : 0u;
        __syncthreads();
        s[t] += u;
        __syncthreads();
    }
    g_hist[base + t] = s[t] - v;                 // exclusive within chunk
    if (t == 1023) g_chunk[blockIdx.x] = s[1023];
}

// ---- K3: exclusive scan of the 256 chunk totals ----
__global__ void k_scan_top() {
    __shared__ uint32_t s[NCHUNK];
    const int t = threadIdx.x;
    const uint32_t v = g_chunk[t];
    s[t] = v;
    __syncthreads();
    #pragma unroll
    for (int o = 1; o < NCHUNK; o <<= 1) {
        uint32_t u = (t >= o) ? s[t - o] : 0u;
        __syncthreads();
        s[t] += u;
        __syncthreads();
    }
    g_chunk[t] = s[t] - v;
}

// ---- K4: scatter sorted point records (coords + original idx) ----
__global__ void k_scatter(const float* __restrict__ x, int B) {
    int b = blockIdx.x * blockDim.x + threadIdx.x;
    if (b >= B) return;
    const float p0 = x[3 * b + 0];
    const float p1 = x[3 * b + 1];
    const float p2 = x[3 * b + 2];
    const uint32_t m = morton64(p0, p1, p2);
    const uint32_t pos = g_chunk[m >> 10] + atomicAdd(&g_hist[m], 1u);
    __stcs(&g_pts[pos], make_float4(p0, p1, p2, __uint_as_float((uint32_t)b)));
}

// ---- gather: one level, plain 8x LDG.64 ----
__device__ __forceinline__ void level_gather(
    float p0, float p1, float p2, int R, const float2* __restrict__ tab,
    float& a0, float& a1)
{
    const float scale = 0.5f * (float)R;
    const float r0 = (p0 + 1.0f) * scale;
    const float r1 = (p1 + 1.0f) * scale;
    const float r2 = (p2 + 1.0f) * scale;

    float f0 = floorf(r0);
    float f1 = floorf(r1);
    float f2 = floorf(r2);
    const float rmax = (float)(R - 1);
    f0 = fminf(fmaxf(f0, 0.0f), rmax);
    f1 = fminf(fmaxf(f1, 0.0f), rmax);
    f2 = fminf(fmaxf(f2, 0.0f), rmax);

    const float w0 = r0 - f0, w1 = r1 - f1, w2 = r2 - f2;
    const float u0 = 1.0f - w0, u1 = 1.0f - w1, u2 = 1.0f - w2;

    const uint32_t i0 = (uint32_t)f0;
    const uint32_t i1 = (uint32_t)f1;
    const uint32_t i2 = (uint32_t)f2;

    const uint32_t xa = i0;
    const uint32_t xb = i0 + 1u;
    const uint32_t ya = i1 * PRIME_Y;
    const uint32_t yb = ya + PRIME_Y;
    const uint32_t za = i2 * PRIME_Z;
    const uint32_t zb = za + PRIME_Z;

    const float2 v000 = __ldg(&tab[(xa ^ ya ^ za) & TMASK]);
    const float2 v100 = __ldg(&tab[(xb ^ ya ^ za) & TMASK]);
    const float2 v010 = __ldg(&tab[(xa ^ yb ^ za) & TMASK]);
    const float2 v110 = __ldg(&tab[(xb ^ yb ^ za) & TMASK]);
    const float2 v001 = __ldg(&tab[(xa ^ ya ^ zb) & TMASK]);
    const float2 v101 = __ldg(&tab[(xb ^ ya ^ zb) & TMASK]);
    const float2 v011 = __ldg(&tab[(xa ^ yb ^ zb) & TMASK]);
    const float2 v111 = __ldg(&tab[(xb ^ yb ^ zb) & TMASK]);

    const float w000 = u0 * u1 * u2;
    const float w100 = w0 * u1 * u2;
    const float w010 = u0 * w1 * u2;
    const float w110 = w0 * w1 * u2;
    const float w001 = u0 * u1 * w2;
    const float w101 = w0 * u1 * w2;
    const float w011 = u0 * w1 * w2;
    const float w111 = w0 * w1 * w2;

    a0 = w000 * v000.x;
    a1 = w000 * v000.y;
    a0 = fmaf(w100, v100.x, a0);  a1 = fmaf(w100, v100.y, a1);
    a0 = fmaf(w010, v010.x, a0);  a1 = fmaf(w010, v010.y, a1);
    a0 = fmaf(w110, v110.x, a0);  a1 = fmaf(w110, v110.y, a1);
    a0 = fmaf(w001, v001.x, a0);  a1 = fmaf(w001, v001.y, a1);
    a0 = fmaf(w101, v101.x, a0);  a1 = fmaf(w101, v101.y, a1);
    a0 = fmaf(w011, v011.x, a0);  a1 = fmaf(w011, v011.y, a1);
    a0 = fmaf(w111, v111.x, a0);  a1 = fmaf(w111, v111.y, a1);
}

// ---- K5: main gather, 4 levels per iteration (32 loads in flight) ----
__global__ __launch_bounds__(256, 2) void hash_embed_kernel(
    const float* __restrict__ emb,
    float* __restrict__ out,
    int B)
{
    int b = blockIdx.x * blockDim.x + threadIdx.x;
    if (b >= B) return;

    const float4 pt = __ldg(&g_pts[b]);          // fully coalesced point read
    const float p0 = pt.x, p1 = pt.y, p2 = pt.z;
    const uint32_t idx = __float_as_uint(pt.w);

    float4* __restrict__ o = reinterpret_cast<float4*>(out) + (size_t)idx * 8;

    // 4 iterations x 4 levels: 32 outstanding gathers per thread to keep the
    // L1tex wavefront pipe saturated (round-6's 16 left ~15% idle); 128-reg
    // budget via (256,2).
    #pragma unroll 1
    for (int g = 0; g < NLVL / 4; ++g) {
        const int l0 = 4 * g;
        const float2* __restrict__ tab0 =
            reinterpret_cast<const float2*>(emb) + (size_t)l0 * TSZ;

        float a0, a1, a2, a3, a4, a5, a6, a7;
        level_gather(p0, p1, p2, c_res[l0],     tab0,           a0, a1);
        level_gather(p0, p1, p2, c_res[l0 + 1], tab0 + TSZ,     a2, a3);
        level_gather(p0, p1, p2, c_res[l0 + 2], tab0 + 2 * TSZ, a4, a5);
        level_gather(p0, p1, p2, c_res[l0 + 3], tab0 + 3 * TSZ, a6, a7);

        __stcs(&o[2 * g + 0], make_float4(a0, a1, a2, a3));
        __stcs(&o[2 * g + 1], make_float4(a4, a5, a6, a7));
    }
}

extern "C" void kernel_launch(void* const* d_in, const int* in_sizes, int n_in,
                              void* d_out, int out_size)
{
    const float* x   = (const float*)d_in[0];   // (B, 3) f32
    const float* emb = (const float*)d_in[1];   // (16, 2^19, 2) f32
    float* out = (float*)d_out;                 // (B, 32) f32

    const int B = in_sizes[0] / 3;
    const int threads = 256;
    const int blocks = (B + threads - 1) / threads;

    void* hist_ptr = nullptr;
    cudaGetSymbolAddress(&hist_ptr, g_hist);
    cudaMemsetAsync(hist_ptr, 0, NBINS * sizeof(uint32_t));

    k_hist<<<blocks, threads>>>(x, B);
    k_scan_chunks<<<NCHUNK, 1024>>>();
    k_scan_top<<<1, NCHUNK>>>();
    k_scatter<<<blocks, threads>>>(x, B);
    hash_embed_kernel<<<blocks, threads>>>(emb, out, B);
}

// round 16
// speedup vs baseline: 1.4495x; 1.0836x over previous
#include <cuda_runtime.h>
#include <cstdint>

#define NLVL 16
#define TSZ (1 << 19)
#define TMASK ((1u << 19) - 1u)
#define PRIME_Y 2654435761u
#define PRIME_Z 805459861u

#define BMAX (1 << 20)          // BSZ = 1048576
#define NBINS (1 << 18)         // 64^3 morton bins (proven config)
#define NCHUNK (NBINS / 1024)   // 256

// ---- scratch (device globals; no allocation allowed) ----
__device__ uint32_t g_hist[NBINS];   // histogram -> scanned offsets -> cursors
__device__ uint32_t g_chunk[NCHUNK]; // chunk totals -> exclusive scanned
__device__ float4   g_pts[BMAX];     // sorted (p0,p1,p2, bitcast(orig idx))

// floor(16 * 2^(i/3)); ambiguous i=3,6,9,12,15 -> power-of-two branch
// (validated rel_err 3.9e-8).
__constant__ int c_res[NLVL] = {16, 20, 25, 32, 40, 50, 64, 80,
                                101, 128, 161, 203, 256, 322, 406, 512};

__device__ __forceinline__ uint32_t spread3(uint32_t v) {
    v &= 0x3FFu;
    v = (v | (v << 16)) & 0x030000FFu;
    v = (v | (v << 8))  & 0x0300F00Fu;
    v = (v | (v << 4))  & 0x030C30C3u;
    v = (v | (v << 2))  & 0x09249249u;
    return v;
}

__device__ __forceinline__ uint32_t morton64(float p0, float p1, float p2) {
    uint32_t c0 = (uint32_t)fminf(fmaxf(floorf((p0 + 1.0f) * 32.0f), 0.0f), 63.0f);
    uint32_t c1 = (uint32_t)fminf(fmaxf(floorf((p1 + 1.0f) * 32.0f), 0.0f), 63.0f);
    uint32_t c2 = (uint32_t)fminf(fmaxf(floorf((p2 + 1.0f) * 32.0f), 0.0f), 63.0f);
    return spread3(c0) | (spread3(c1) << 1) | (spread3(c2) << 2);
}

// ---- K1: histogram ----
__global__ void k_hist(const float* __restrict__ x, int B) {
    int b = blockIdx.x * blockDim.x + threadIdx.x;
    if (b >= B) return;
    atomicAdd(&g_hist[morton64(x[3 * b], x[3 * b + 1], x[3 * b + 2])], 1u);
}

// ---- K2: per-1024-bin chunk exclusive scan (in place) + chunk totals ----
__global__ void k_scan_chunks() {
    __shared__ uint32_t s[1024];
    const int t = threadIdx.x;
    const int base = blockIdx.x * 1024;
    const uint32_t v = g_hist[base + t];
    s[t] = v;
    __syncthreads();
    #pragma unroll
    for (int o = 1; o < 1024; o <<= 1) {
        uint32_t u = (t >= o) ? s[t - o] : 0u;
        __syncthreads();
        s[t] += u;
        __syncthreads();
    }
    g_hist[base + t] = s[t] - v;                 // exclusive within chunk
    if (t == 1023) g_chunk[blockIdx.x] = s[1023];
}

// ---- K3: exclusive scan of the 256 chunk totals ----
__global__ void k_scan_top() {
    __shared__ uint32_t s[NCHUNK];
    const int t = threadIdx.x;
    const uint32_t v = g_chunk[t];
    s[t] = v;
    __syncthreads();
    #pragma unroll
    for (int o = 1; o < NCHUNK; o <<= 1) {
        uint32_t u = (t >= o) ? s[t - o] : 0u;
        __syncthreads();
        s[t] += u;
        __syncthreads();
    }
    g_chunk[t] = s[t] - v;
}

// ---- K4: scatter sorted point records (coords + original idx) ----
__global__ void k_scatter(const float* __restrict__ x, int B) {
    int b = blockIdx.x * blockDim.x + threadIdx.x;
    if (b >= B) return;
    const float p0 = x[3 * b + 0];
    const float p1 = x[3 * b + 1];
    const float p2 = x[3 * b + 2];
    const uint32_t m = morton64(p0, p1, p2);
    const uint32_t pos = g_chunk[m >> 10] + atomicAdd(&g_hist[m], 1u);
    __stcs(&g_pts[pos], make_float4(p0, p1, p2, __uint_as_float((uint32_t)b)));
}

// ---- gather: one level, plain 8x LDG.64 ----
__device__ __forceinline__ void level_gather(
    float p0, float p1, float p2, int R, const float2* __restrict__ tab,
    float& a0, float& a1)
{
    const float scale = 0.5f * (float)R;
    const float r0 = (p0 + 1.0f) * scale;
    const float r1 = (p1 + 1.0f) * scale;
    const float r2 = (p2 + 1.0f) * scale;

    float f0 = floorf(r0);
    float f1 = floorf(r1);
    float f2 = floorf(r2);
    const float rmax = (float)(R - 1);
    f0 = fminf(fmaxf(f0, 0.0f), rmax);
    f1 = fminf(fmaxf(f1, 0.0f), rmax);
    f2 = fminf(fmaxf(f2, 0.0f), rmax);

    const float w0 = r0 - f0, w1 = r1 - f1, w2 = r2 - f2;
    const float u0 = 1.0f - w0, u1 = 1.0f - w1, u2 = 1.0f - w2;

    const uint32_t i0 = (uint32_t)f0;
    const uint32_t i1 = (uint32_t)f1;
    const uint32_t i2 = (uint32_t)f2;

    const uint32_t xa = i0;
    const uint32_t xb = i0 + 1u;
    const uint32_t ya = i1 * PRIME_Y;
    const uint32_t yb = ya + PRIME_Y;
    const uint32_t za = i2 * PRIME_Z;
    const uint32_t zb = za + PRIME_Z;

    const float2 v000 = __ldg(&tab[(xa ^ ya ^ za) & TMASK]);
    const float2 v100 = __ldg(&tab[(xb ^ ya ^ za) & TMASK]);
    const float2 v010 = __ldg(&tab[(xa ^ yb ^ za) & TMASK]);
    const float2 v110 = __ldg(&tab[(xb ^ yb ^ za) & TMASK]);
    const float2 v001 = __ldg(&tab[(xa ^ ya ^ zb) & TMASK]);
    const float2 v101 = __ldg(&tab[(xb ^ ya ^ zb) & TMASK]);
    const float2 v011 = __ldg(&tab[(xa ^ yb ^ zb) & TMASK]);
    const float2 v111 = __ldg(&tab[(xb ^ yb ^ zb) & TMASK]);

    const float w000 = u0 * u1 * u2;
    const float w100 = w0 * u1 * u2;
    const float w010 = u0 * w1 * u2;
    const float w110 = w0 * w1 * u2;
    const float w001 = u0 * u1 * w2;
    const float w101 = w0 * u1 * w2;
    const float w011 = u0 * w1 * w2;
    const float w111 = w0 * w1 * w2;

    a0 = w000 * v000.x;
    a1 = w000 * v000.y;
    a0 = fmaf(w100, v100.x, a0);  a1 = fmaf(w100, v100.y, a1);
    a0 = fmaf(w010, v010.x, a0);  a1 = fmaf(w010, v010.y, a1);
    a0 = fmaf(w110, v110.x, a0);  a1 = fmaf(w110, v110.y, a1);
    a0 = fmaf(w001, v001.x, a0);  a1 = fmaf(w001, v001.y, a1);
    a0 = fmaf(w101, v101.x, a0);  a1 = fmaf(w101, v101.y, a1);
    a0 = fmaf(w011, v011.x, a0);  a1 = fmaf(w011, v011.y, a1);
    a0 = fmaf(w111, v111.x, a0);  a1 = fmaf(w111, v111.y, a1);
}

#define SPAD 33   // smem row stride (floats): conflict-free for STS.32 and LDS.32

// ---- K5: gather + smem-staged transposed store (1 store-wf per row) ----
__global__ __launch_bounds__(256, 2) void hash_embed_kernel(
    const float* __restrict__ emb,
    float* __restrict__ out,
    int B)
{
    __shared__ float srow[256 * SPAD];

    int b = blockIdx.x * blockDim.x + threadIdx.x;
    if (b >= B) b = B - 1;              // clamp: warps stay full; duplicate
                                        // lanes rewrite identical values

    const float4 pt = __ldg(&g_pts[b]);
    const float p0 = pt.x, p1 = pt.y, p2 = pt.z;
    const uint32_t idx = __float_as_uint(pt.w);

    float* __restrict__ my = &srow[threadIdx.x * SPAD];

    // 4 iterations x 4 levels: 32 outstanding gathers per thread; results go
    // straight to smem (no 32-reg accumulator carry across the loop).
    #pragma unroll 1
    for (int g = 0; g < NLVL / 4; ++g) {
        const int l0 = 4 * g;
        const float2* __restrict__ tab0 =
            reinterpret_cast<const float2*>(emb) + (size_t)l0 * TSZ;

        float a0, a1, a2, a3, a4, a5, a6, a7;
        level_gather(p0, p1, p2, c_res[l0],     tab0,           a0, a1);
        level_gather(p0, p1, p2, c_res[l0 + 1], tab0 + TSZ,     a2, a3);
        level_gather(p0, p1, p2, c_res[l0 + 2], tab0 + 2 * TSZ, a4, a5);
        level_gather(p0, p1, p2, c_res[l0 + 3], tab0 + 3 * TSZ, a6, a7);

        my[8 * g + 0] = a0;  my[8 * g + 1] = a1;
        my[8 * g + 2] = a2;  my[8 * g + 3] = a3;
        my[8 * g + 4] = a4;  my[8 * g + 5] = a5;
        my[8 * g + 6] = a6;  my[8 * g + 7] = a7;
    }

    // Transposed cooperative store: for each of this warp's 32 rows, all 32
    // lanes write one coalesced 128B line (1 store wavefront per row, vs 8
    // scattered STG.128 wavefronts per row in the old layout).
    __syncwarp();
    const int lane = threadIdx.x & 31;
    const int wbase = threadIdx.x & ~31;          // first thread of my warp
    #pragma unroll 4
    for (int r = 0; r < 32; ++r) {
        const uint32_t idx_r = __shfl_sync(0xFFFFFFFFu, idx, r);
        const float v = srow[(wbase + r) * SPAD + lane];
        __stcs(&out[(size_t)idx_r * 32 + lane], v);
    }
}

extern "C" void kernel_launch(void* const* d_in, const int* in_sizes, int n_in,
                              void* d_out, int out_size)
{
    const float* x   = (const float*)d_in[0];   // (B, 3) f32
    const float* emb = (const float*)d_in[1];   // (16, 2^19, 2) f32
    float* out = (float*)d_out;                 // (B, 32) f32

    const int B = in_sizes[0] / 3;
    const int threads = 256;
    const int blocks = (B + threads - 1) / threads;

    void* hist_ptr = nullptr;
    cudaGetSymbolAddress(&hist_ptr, g_hist);
    cudaMemsetAsync(hist_ptr, 0, NBINS * sizeof(uint32_t));

    k_hist<<<blocks, threads>>>(x, B);
    k_scan_chunks<<<NCHUNK, 1024>>>();
    k_scan_top<<<1, NCHUNK>>>();
    k_scatter<<<blocks, threads>>>(x, B);
    hash_embed_kernel<<<blocks, threads>>>(emb, out, B);
}